// round 12
// baseline (speedup 1.0000x reference)
#include <cuda_runtime.h>
#include <cstdint>

#define LMAX  6
#define BATCH 1024
#define F     64
#define IR    455
#define NROT  64
#define FS    (F * IR)   // 29120 floats per batch element

// Raw packed pre-scaled weights W_l[k, n] (f32), k=(f*d+u), n=(g*d+v).
__device__ float g_W[4096 * 455];
// Fragment-ordered bf16x2 hi/lo planes of W.
// Per l (offset 4096*off[l] u32): [ktile(4d)][bn(d)][plane(2)][wt(2)][c(2)][lane(32)][j(4)]
__device__ uint32_t g_Wf[4096 * 455];

// Tile decode tables, ordered l = 6..0 (largest K first).
__constant__ int c_cnt[7]  = {1352, 968, 648, 392, 200, 72, 8}; // 8*d*d
__constant__ int c_d[7]    = {13, 11, 9, 7, 5, 3, 1};
__constant__ int c_off[7]  = {286, 165, 84, 35, 10, 1, 0};

// ---------------------------------------------------------------------------
// helpers
// ---------------------------------------------------------------------------
__device__ __forceinline__ uint32_t pack_bf16x2(float lo_e, float hi_e) {
    uint32_t r;
    asm("cvt.rn.bf16x2.f32 %0, %1, %2;" : "=r"(r) : "f"(hi_e), "f"(lo_e));
    return r;
}
__device__ __forceinline__ float bf16_lo_f32(uint32_t p) { return __uint_as_float(p << 16); }
__device__ __forceinline__ float bf16_hi_f32(uint32_t p) { return __uint_as_float(p & 0xffff0000u); }

__device__ __forceinline__ uint32_t split_pack(float e0, float e1, uint32_t& lo_out) {
    uint32_t hi = pack_bf16x2(e0, e1);
    lo_out = pack_bf16x2(e0 - bf16_lo_f32(hi), e1 - bf16_hi_f32(hi));
    return hi;
}

__device__ __forceinline__ void mma_bf16(float c[4],
                                         const uint32_t a[4],
                                         const uint32_t b[2])
{
    asm volatile(
        "mma.sync.aligned.m16n8k16.row.col.f32.bf16.bf16.f32 "
        "{%0,%1,%2,%3}, {%4,%5,%6,%7}, {%8,%9}, {%0,%1,%2,%3};"
        : "+f"(c[0]), "+f"(c[1]), "+f"(c[2]), "+f"(c[3])
        : "r"(a[0]), "r"(a[1]), "r"(a[2]), "r"(a[3]), "r"(b[0]), "r"(b[1]));
}

__device__ __forceinline__ void cp16(uint32_t s, const void* g) {
    asm volatile("cp.async.cg.shared.global [%0], [%1], 16;" :: "r"(s), "l"(g));
}
__device__ __forceinline__ void cp_commit() { asm volatile("cp.async.commit_group;"); }
template <int W>
__device__ __forceinline__ void cp_wait() { asm volatile("cp.async.wait_group %0;" :: "n"(W)); }

// ---------------------------------------------------------------------------
// Kernel 1: psi GEMM.  C[fg, i] = sum_r w[fg, r] * D[r, i], scattered into g_W.
// grid = (8, 64)
// ---------------------------------------------------------------------------
__global__ void __launch_bounds__(256) build_w2_kernel(const float* __restrict__ D,
                                                       const float* __restrict__ w)
{
    const int dtab[7] = {1, 3, 5, 7, 9, 11, 13};
    const int otab[7] = {0, 1, 10, 35, 84, 165, 286};

    __shared__ float Wsh[64][68];
    __shared__ float Dsh[64][68];

    const int t   = threadIdx.x;
    const int fg0 = blockIdx.y * 64;
    const int i0  = blockIdx.x * 64;

    for (int idx = t; idx < 4096; idx += 256) {
        int row = idx >> 6, r = idx & 63;
        Wsh[r][row] = w[(fg0 + row) * 64 + r];
    }
    for (int idx = t; idx < 4096; idx += 256) {
        int r = idx >> 6, c = idx & 63;
        int i = i0 + c;
        Dsh[r][c] = (i < IR) ? D[r * IR + i] : 0.0f;
    }
    __syncthreads();

    const int ty = t >> 4, tx = t & 15;
    float acc[4][4] = {};

#pragma unroll 4
    for (int r = 0; r < 64; ++r) {
        float4 a4 = *(const float4*)&Wsh[r][ty * 4];
        float4 b4 = *(const float4*)&Dsh[r][tx * 4];
        float av[4] = {a4.x, a4.y, a4.z, a4.w};
        float bv[4] = {b4.x, b4.y, b4.z, b4.w};
#pragma unroll
        for (int i = 0; i < 4; ++i)
#pragma unroll
            for (int j = 0; j < 4; ++j)
                acc[i][j] += av[i] * bv[j];
    }

#pragma unroll
    for (int j = 0; j < 4; ++j) {
        const int i = i0 + tx * 4 + j;
        if (i >= IR) continue;
        int l = 0;
#pragma unroll
        for (int q = 1; q < 7; ++q)
            if (i >= otab[q]) l = q;
        const int d = dtab[l], off = otab[l];
        const int jj = i - off;
        const int u = jj / d, v = jj - u * d;
        const float scale = rsqrtf((float)d) * (1.0f / 64.0f);
        const int base = 4096 * off;
        const int N = 64 * d;
#pragma unroll
        for (int i4 = 0; i4 < 4; ++i4) {
            const int fg = fg0 + ty * 4 + i4;
            const int f = fg >> 6, gg = fg & 63;
            g_W[base + (f * d + u) * N + gg * d + v] = scale * acc[i4][j];
        }
    }
}

// ---------------------------------------------------------------------------
// Kernel 1b: pack g_W into fragment-ordered bf16x2 hi/lo planes (g_Wf).
// grid = (2704, 7), guard idx < 4096*d*d.
// ---------------------------------------------------------------------------
__global__ void __launch_bounds__(256) pack_w2_kernel()
{
    const int dtab[7] = {1, 3, 5, 7, 9, 11, 13};
    const int otab[7] = {0, 1, 10, 35, 84, 165, 286};

    const int l = blockIdx.y;
    const int d = dtab[l];
    const int off = otab[l];
    const int N = 64 * d;
    const int tot = 4096 * d * d;
    const int idx = blockIdx.x * 256 + threadIdx.x;
    if (idx >= tot) return;

    const int j    = idx & 3;
    const int lane = (idx >> 2) & 31;
    const int c    = (idx >> 7) & 1;
    const int wt   = (idx >> 8) & 1;
    const int pl   = (idx >> 9) & 1;
    const int rest = idx >> 10;
    const int bn   = rest % d;
    const int kt   = rest / d;

    const int g  = lane >> 2;
    const int tg = lane & 3;
    const int k2 = kt * 8 + tg + 4 * (j & 1);
    const int n  = bn * 64 + wt * 32 + (2 * c + (j >> 1)) * 8 + g;

    const float e0 = g_W[4096 * off + (2 * k2) * N + n];
    const float e1 = g_W[4096 * off + (2 * k2 + 1) * N + n];
    uint32_t lo;
    uint32_t hi = split_pack(e0, e1, lo);
    g_Wf[4096 * off + idx] = pl ? lo : hi;
}

// ---------------------------------------------------------------------------
// Kernel 2: fused GEMM, bf16x2-split, fragment-ordered operands,
// direct-LDG A staging, double-buffered dynamic smem, BK=64: one
// __syncthreads per FOUR k16 sub-tiles (96 MMAs per barrier).
// Block tile 128x64, 256 threads = 8 warps (4x2 of 32x32 warp tiles).
// Dynamic smem: AhF [2][4][1024] | AlF [2][4][1024] | BF [2][4][1024] = 96 KB
// ---------------------------------------------------------------------------
__global__ void __launch_bounds__(256, 2) so3_v7_kernel(const float* __restrict__ x,
                                                        float* __restrict__ out)
{
    extern __shared__ __align__(16) uint32_t dsm[];
    uint32_t* AhF = dsm;             // (s*4+sub)*1024 + slot
    uint32_t* AlF = dsm + 8192;
    uint32_t* BF  = dsm + 16384;

    // ---- decode (l, bm, bn) ----
    int rem = blockIdx.x;
    int li = 0;
#pragma unroll
    for (int q = 0; q < 6; ++q)
        if (rem >= c_cnt[li]) { rem -= c_cnt[li]; li++; }
    const int d    = c_d[li];
    const int offl = c_off[li];
    const int bn   = rem % d;
    const int bm   = rem / d;

    const int t    = threadIdx.x;
    const int wid  = t >> 5;
    const int lane = t & 31;
    const int g    = lane >> 2;
    const int tg   = lane & 3;
    const int wmi  = wid & 3;          // warp m index (32-row tiles)
    const int wt   = wid >> 2;         // warp n half (32 cols)

    // ---- direct A gather mapping: this thread's fragment slot ----
    const int m    = (t >> 5) * 16 + g;
    const int gr0  = bm * 128 + m;
    const int gr8  = gr0 + 8;
    const int b0_  = gr0 / d;
    const int b8_  = gr8 / d;
    const float* base0 = x + b0_ * FS + offl + (gr0 - b0_ * d);
    const float* base8 = x + b8_ * FS + offl + (gr8 - b8_ * d);

    const int q16 = 16 / d;
    const int r16 = 16 - q16 * d;
    const int kl[4] = {2 * tg, 2 * tg + 1, 2 * tg + 8, 2 * tg + 9};
    int uA[4], offA[4];
#pragma unroll
    for (int j = 0; j < 4; ++j) {
        const int f = kl[j] / d;
        uA[j]   = kl[j] - f * d;
        offA[j] = f * IR + uA[j] * d;
    }

    // ---- B staging ----
    const uint32_t* Wsrc = g_Wf + 4096 * offl + bn * 1024 + t * 4;
    const int WstepB = d * 1024;   // u32 per k16 sub-tile

    const uint32_t bf_b = (uint32_t)__cvta_generic_to_shared(BF);
    const uint32_t bsB  = bf_b + t * 16;

    float acc[2][4][4] = {};
    float v[4][8];   // prefetched A for 4 subs

#define LOAD_A(dst)                                                     \
    do {                                                                \
        dst[0] = base0[offA[0]]; dst[1] = base0[offA[1]];               \
        dst[2] = base8[offA[0]]; dst[3] = base8[offA[1]];               \
        dst[4] = base0[offA[2]]; dst[5] = base0[offA[3]];               \
        dst[6] = base8[offA[2]]; dst[7] = base8[offA[3]];               \
        _Pragma("unroll")                                               \
        for (int j = 0; j < 4; ++j) {                                   \
            uA[j] += r16; offA[j] += q16 * IR + r16 * d;                \
            if (uA[j] >= d) { uA[j] -= d; offA[j] += IR - d * d; }      \
        }                                                               \
    } while (0)

    // ---- prologue: LDG A(0) all subs, cp.async B(0) all subs ----
#pragma unroll
    for (int sub = 0; sub < 4; ++sub)
        LOAD_A(v[sub]);
#pragma unroll
    for (int sub = 0; sub < 4; ++sub)
        cp16(bsB + sub * 4096, Wsrc + sub * WstepB);
    cp_commit();
    Wsrc += 4 * WstepB;

    const int ntiles = d;   // K = 64*d, 64 per barrier
    for (int it = 0; it < ntiles; ++it) {
        const int s = it & 1;

        // ---- 1. split + STS all 4 subs into stage s ----
#pragma unroll
        for (int sub = 0; sub < 4; ++sub) {
            uint32_t l0, l1, l2, l3;
            uint32_t h0 = split_pack(v[sub][0], v[sub][1], l0);
            uint32_t h1 = split_pack(v[sub][2], v[sub][3], l1);
            uint32_t h2 = split_pack(v[sub][4], v[sub][5], l2);
            uint32_t h3 = split_pack(v[sub][6], v[sub][7], l3);
            const int slot = (s * 4 + sub) * 1024 + t * 4;
            *(uint4*)&AhF[slot] = make_uint4(h0, h1, h2, h3);
            *(uint4*)&AlF[slot] = make_uint4(l0, l1, l2, l3);
        }

        // ---- 2. prefetch A(it+1), all subs ----
        if (it + 1 < ntiles) {
#pragma unroll
            for (int sub = 0; sub < 4; ++sub)
                LOAD_A(v[sub]);
        }

        // ---- 3. wait B(it), barrier ----
        cp_wait<0>();
        __syncthreads();

        // ---- 4. issue B(it+1) into stage s^1 ----
        if (it + 1 < ntiles) {
#pragma unroll
            for (int sub = 0; sub < 4; ++sub)
                cp16(bsB + (s ^ 1) * 16384 + sub * 4096, Wsrc + sub * WstepB);
            cp_commit();
            Wsrc += 4 * WstepB;
        }

        // ---- 5. fragments + 4x24 MMA on stage s ----
#pragma unroll
        for (int sub = 0; sub < 4; ++sub) {
            const int sb = (s * 4 + sub) * 1024;
            uint32_t ah[2][4], al[2][4], bh[4][2], bl[4][2];
#pragma unroll
            for (int mi = 0; mi < 2; ++mi) {
                const int mt = wmi * 2 + mi;
                uint4 a4 = *(const uint4*)&AhF[sb + (mt * 32 + lane) * 4];
                ah[mi][0] = a4.x; ah[mi][1] = a4.y; ah[mi][2] = a4.z; ah[mi][3] = a4.w;
                uint4 b4 = *(const uint4*)&AlF[sb + (mt * 32 + lane) * 4];
                al[mi][0] = b4.x; al[mi][1] = b4.y; al[mi][2] = b4.z; al[mi][3] = b4.w;
            }
#pragma unroll
            for (int p = 0; p < 2; ++p) {
                uint32_t (*bf)[2] = p ? bl : bh;
                uint4 q0 = *(const uint4*)&BF[sb + p * 512 + wt * 256 + lane * 4];
                uint4 q1 = *(const uint4*)&BF[sb + p * 512 + wt * 256 + 128 + lane * 4];
                bf[0][0] = q0.x; bf[0][1] = q0.y; bf[1][0] = q0.z; bf[1][1] = q0.w;
                bf[2][0] = q1.x; bf[2][1] = q1.y; bf[3][0] = q1.z; bf[3][1] = q1.w;
            }
#pragma unroll
            for (int mi = 0; mi < 2; ++mi)
#pragma unroll
                for (int ni = 0; ni < 4; ++ni) {
                    mma_bf16(acc[mi][ni], ah[mi], bh[ni]);   // hi*hi
                    mma_bf16(acc[mi][ni], ah[mi], bl[ni]);   // hi*lo
                    mma_bf16(acc[mi][ni], al[mi], bh[ni]);   // lo*hi
                }
        }
        // stage-s reads complete before barrier(it+1), which precedes the
        // stage-s overwrite at it+2. Same hazard ordering as v6.
    }

#undef LOAD_A

    // ---- epilogue: scatter into out[b, g, off + v*d + m] ----
#pragma unroll
    for (int mi = 0; mi < 2; ++mi) {
#pragma unroll
        for (int cr = 0; cr < 2; ++cr) {
            const int row = bm * 128 + wmi * 32 + mi * 16 + g + cr * 8;
            const int b = row / d;
            const int mm = row - b * d;
            float* ob = out + b * FS + offl + mm;
#pragma unroll
            for (int ni = 0; ni < 4; ++ni) {
#pragma unroll
                for (int cc = 0; cc < 2; ++cc) {
                    const int col = bn * 64 + wt * 32 + ni * 8 + tg * 2 + cc;
                    const int gg = col / d;
                    const int vv = col - gg * d;
                    ob[gg * IR + vv * d] = acc[mi][ni][cr * 2 + cc];
                }
            }
        }
    }
}

// ---------------------------------------------------------------------------
extern "C" void kernel_launch(void* const* d_in, const int* in_sizes, int n_in,
                              void* d_out, int out_size)
{
    const float* x = nullptr;
    const float* D = nullptr;
    const float* w = nullptr;
    for (int i = 0; i < n_in; ++i) {
        if (in_sizes[i] == NROT * IR)         D = (const float*)d_in[i];
        else if (in_sizes[i] == F * F * NROT) w = (const float*)d_in[i];
        else                                  x = (const float*)d_in[i];
    }
    float* out = (float*)d_out;

    static bool attr_done = false;
    if (!attr_done) {
        cudaFuncSetAttribute(so3_v7_kernel,
                             cudaFuncAttributeMaxDynamicSharedMemorySize, 98304);
        attr_done = true;
    }

    build_w2_kernel<<<dim3(8, 64), 256>>>(D, w);
    pack_w2_kernel<<<dim3(2704, LMAX + 1), 256>>>();
    so3_v7_kernel<<<3640, 256, 98304>>>(x, out);
}

// round 13
// speedup vs baseline: 1.4809x; 1.4809x over previous
#include <cuda_runtime.h>
#include <cstdint>

#define LMAX  6
#define BATCH 1024
#define F     64
#define IR    455
#define NROT  64
#define FS    (F * IR)   // 29120 floats per batch element

// Raw packed pre-scaled weights W_l[k, n] (f32), k=(f*d+u), n=(g*d+v).
__device__ float g_W[4096 * 455];
// Fragment-ordered bf16x2 hi/lo planes of W.
// Per l (offset 4096*off[l] u32): [ktile(4d)][bn(d)][plane(2)][wt(2)][c(2)][lane(32)][j(4)]
__device__ uint32_t g_Wf[4096 * 455];

// Tile decode tables, ordered l = 6..0 (largest K first).
__constant__ int c_cnt[7]  = {1352, 968, 648, 392, 200, 72, 8}; // 8*d*d
__constant__ int c_d[7]    = {13, 11, 9, 7, 5, 3, 1};
__constant__ int c_off[7]  = {286, 165, 84, 35, 10, 1, 0};

// ---------------------------------------------------------------------------
// helpers
// ---------------------------------------------------------------------------
__device__ __forceinline__ uint32_t pack_bf16x2(float lo_e, float hi_e) {
    uint32_t r;
    asm("cvt.rn.bf16x2.f32 %0, %1, %2;" : "=r"(r) : "f"(hi_e), "f"(lo_e));
    return r;
}
__device__ __forceinline__ float bf16_lo_f32(uint32_t p) { return __uint_as_float(p << 16); }
__device__ __forceinline__ float bf16_hi_f32(uint32_t p) { return __uint_as_float(p & 0xffff0000u); }

__device__ __forceinline__ uint32_t split_pack(float e0, float e1, uint32_t& lo_out) {
    uint32_t hi = pack_bf16x2(e0, e1);
    lo_out = pack_bf16x2(e0 - bf16_lo_f32(hi), e1 - bf16_hi_f32(hi));
    return hi;
}

__device__ __forceinline__ void mma_bf16(float c[4],
                                         const uint32_t a[4],
                                         const uint32_t b[2])
{
    asm volatile(
        "mma.sync.aligned.m16n8k16.row.col.f32.bf16.bf16.f32 "
        "{%0,%1,%2,%3}, {%4,%5,%6,%7}, {%8,%9}, {%0,%1,%2,%3};"
        : "+f"(c[0]), "+f"(c[1]), "+f"(c[2]), "+f"(c[3])
        : "r"(a[0]), "r"(a[1]), "r"(a[2]), "r"(a[3]), "r"(b[0]), "r"(b[1]));
}

__device__ __forceinline__ void cp16(uint32_t s, const void* g) {
    asm volatile("cp.async.cg.shared.global [%0], [%1], 16;" :: "r"(s), "l"(g));
}
__device__ __forceinline__ void cp_commit() { asm volatile("cp.async.commit_group;"); }
template <int W>
__device__ __forceinline__ void cp_wait() { asm volatile("cp.async.wait_group %0;" :: "n"(W)); }

// ---------------------------------------------------------------------------
// Kernel 1: psi GEMM.  C[fg, i] = sum_r w[fg, r] * D[r, i], scattered into g_W.
// grid = (8, 64)
// ---------------------------------------------------------------------------
__global__ void __launch_bounds__(256) build_w2_kernel(const float* __restrict__ D,
                                                       const float* __restrict__ w)
{
    const int dtab[7] = {1, 3, 5, 7, 9, 11, 13};
    const int otab[7] = {0, 1, 10, 35, 84, 165, 286};

    __shared__ float Wsh[64][68];
    __shared__ float Dsh[64][68];

    const int t   = threadIdx.x;
    const int fg0 = blockIdx.y * 64;
    const int i0  = blockIdx.x * 64;

    for (int idx = t; idx < 4096; idx += 256) {
        int row = idx >> 6, r = idx & 63;
        Wsh[r][row] = w[(fg0 + row) * 64 + r];
    }
    for (int idx = t; idx < 4096; idx += 256) {
        int r = idx >> 6, c = idx & 63;
        int i = i0 + c;
        Dsh[r][c] = (i < IR) ? D[r * IR + i] : 0.0f;
    }
    __syncthreads();

    const int ty = t >> 4, tx = t & 15;
    float acc[4][4] = {};

#pragma unroll 4
    for (int r = 0; r < 64; ++r) {
        float4 a4 = *(const float4*)&Wsh[r][ty * 4];
        float4 b4 = *(const float4*)&Dsh[r][tx * 4];
        float av[4] = {a4.x, a4.y, a4.z, a4.w};
        float bv[4] = {b4.x, b4.y, b4.z, b4.w};
#pragma unroll
        for (int i = 0; i < 4; ++i)
#pragma unroll
            for (int j = 0; j < 4; ++j)
                acc[i][j] += av[i] * bv[j];
    }

#pragma unroll
    for (int j = 0; j < 4; ++j) {
        const int i = i0 + tx * 4 + j;
        if (i >= IR) continue;
        int l = 0;
#pragma unroll
        for (int q = 1; q < 7; ++q)
            if (i >= otab[q]) l = q;
        const int d = dtab[l], off = otab[l];
        const int jj = i - off;
        const int u = jj / d, v = jj - u * d;
        const float scale = rsqrtf((float)d) * (1.0f / 64.0f);
        const int base = 4096 * off;
        const int N = 64 * d;
#pragma unroll
        for (int i4 = 0; i4 < 4; ++i4) {
            const int fg = fg0 + ty * 4 + i4;
            const int f = fg >> 6, gg = fg & 63;
            g_W[base + (f * d + u) * N + gg * d + v] = scale * acc[i4][j];
        }
    }
}

// ---------------------------------------------------------------------------
// Kernel 1b: pack g_W into fragment-ordered bf16x2 hi/lo planes (g_Wf).
// grid = (2704, 7), guard idx < 4096*d*d.
// ---------------------------------------------------------------------------
__global__ void __launch_bounds__(256) pack_w2_kernel()
{
    const int dtab[7] = {1, 3, 5, 7, 9, 11, 13};
    const int otab[7] = {0, 1, 10, 35, 84, 165, 286};

    const int l = blockIdx.y;
    const int d = dtab[l];
    const int off = otab[l];
    const int N = 64 * d;
    const int tot = 4096 * d * d;
    const int idx = blockIdx.x * 256 + threadIdx.x;
    if (idx >= tot) return;

    const int j    = idx & 3;
    const int lane = (idx >> 2) & 31;
    const int c    = (idx >> 7) & 1;
    const int wt   = (idx >> 8) & 1;
    const int pl   = (idx >> 9) & 1;
    const int rest = idx >> 10;
    const int bn   = rest % d;
    const int kt   = rest / d;

    const int g  = lane >> 2;
    const int tg = lane & 3;
    const int k2 = kt * 8 + tg + 4 * (j & 1);
    const int n  = bn * 64 + wt * 32 + (2 * c + (j >> 1)) * 8 + g;

    const float e0 = g_W[4096 * off + (2 * k2) * N + n];
    const float e1 = g_W[4096 * off + (2 * k2 + 1) * N + n];
    uint32_t lo;
    uint32_t hi = split_pack(e0, e1, lo);
    g_Wf[4096 * off + idx] = pl ? lo : hi;
}

// ---------------------------------------------------------------------------
// Kernel 2: fused GEMM, bf16x2-split, fragment-ordered operands,
// direct-LDG A staging, double-buffered smem, BK=32, term-major MMA order
// (consecutive MMAs hit distinct accumulators -> no RAW stalls on tensor pipe).
// Block tile 128x64, 256 threads = 8 warps (4x2 of 32x32 warp tiles).
// ---------------------------------------------------------------------------
__global__ void __launch_bounds__(256) so3_v8_kernel(const float* __restrict__ x,
                                                     float* __restrict__ out)
{
    // ---- decode (l, bm, bn) ----
    int rem = blockIdx.x;
    int li = 0;
#pragma unroll
    for (int q = 0; q < 6; ++q)
        if (rem >= c_cnt[li]) { rem -= c_cnt[li]; li++; }
    const int d    = c_d[li];
    const int offl = c_off[li];
    const int bn   = rem % d;
    const int bm   = rem / d;

    const int K = 64 * d;

    // [stage][sub][1024], 16B-stride-per-lane fragment order (conflict-free)
    __shared__ __align__(16) uint32_t AhF[2][2][1024];   // 16 KB
    __shared__ __align__(16) uint32_t AlF[2][2][1024];   // 16 KB
    __shared__ __align__(16) uint32_t BF [2][2][1024];   // 16 KB

    const int t    = threadIdx.x;
    const int wid  = t >> 5;
    const int lane = t & 31;
    const int g    = lane >> 2;
    const int tg   = lane & 3;
    const int wmi  = wid & 3;          // warp m index (32-row tiles)
    const int wt   = wid >> 2;         // warp n half (32 cols)

    // ---- direct A gather mapping: this thread's fragment slot ----
    const int m    = (t >> 5) * 16 + g;
    const int gr0  = bm * 128 + m;
    const int gr8  = gr0 + 8;
    const int b0_  = gr0 / d;
    const int b8_  = gr8 / d;
    const float* base0 = x + b0_ * FS + offl + (gr0 - b0_ * d);
    const float* base8 = x + b8_ * FS + offl + (gr8 - b8_ * d);

    const int q16 = 16 / d;
    const int r16 = 16 - q16 * d;
    const int kl[4] = {2 * tg, 2 * tg + 1, 2 * tg + 8, 2 * tg + 9};
    int uA[4], offA[4];
#pragma unroll
    for (int j = 0; j < 4; ++j) {
        const int f = kl[j] / d;
        uA[j]   = kl[j] - f * d;
        offA[j] = f * IR + uA[j] * d;
    }

    // ---- B staging ----
    const uint32_t* Wsrc = g_Wf + 4096 * offl + bn * 1024 + t * 4;
    const int WstepB = d * 1024;   // u32 per k16 sub-tile

    const uint32_t bf_b = (uint32_t)__cvta_generic_to_shared(&BF[0][0][0]);
    const uint32_t bsB  = bf_b + t * 16;

    float acc[2][4][4] = {};
    float v0[8], v1[8];

#define LOAD_A(dst)                                                     \
    do {                                                                \
        dst[0] = base0[offA[0]]; dst[1] = base0[offA[1]];               \
        dst[2] = base8[offA[0]]; dst[3] = base8[offA[1]];               \
        dst[4] = base0[offA[2]]; dst[5] = base0[offA[3]];               \
        dst[6] = base8[offA[2]]; dst[7] = base8[offA[3]];               \
        _Pragma("unroll")                                               \
        for (int j = 0; j < 4; ++j) {                                   \
            uA[j] += r16; offA[j] += q16 * IR + r16 * d;                \
            if (uA[j] >= d) { uA[j] -= d; offA[j] += IR - d * d; }      \
        }                                                               \
    } while (0)

    // ---- prologue: LDG A(0) subs 0+1, cp.async B(0) subs 0+1 ----
    LOAD_A(v0);
    LOAD_A(v1);
    cp16(bsB, Wsrc);
    cp16(bsB + 4096, Wsrc + WstepB);
    cp_commit();
    Wsrc += 2 * WstepB;

    const int ntiles = K >> 5;   // k32 tiles = 2d
    for (int it = 0; it < ntiles; ++it) {
        const int s = it & 1;

        // ---- 1. split + STS both subs into buffer s ----
        {
            uint32_t l0, l1, l2, l3;
            uint32_t h0 = split_pack(v0[0], v0[1], l0);
            uint32_t h1 = split_pack(v0[2], v0[3], l1);
            uint32_t h2 = split_pack(v0[4], v0[5], l2);
            uint32_t h3 = split_pack(v0[6], v0[7], l3);
            *(uint4*)&AhF[s][0][t * 4] = make_uint4(h0, h1, h2, h3);
            *(uint4*)&AlF[s][0][t * 4] = make_uint4(l0, l1, l2, l3);
            h0 = split_pack(v1[0], v1[1], l0);
            h1 = split_pack(v1[2], v1[3], l1);
            h2 = split_pack(v1[4], v1[5], l2);
            h3 = split_pack(v1[6], v1[7], l3);
            *(uint4*)&AhF[s][1][t * 4] = make_uint4(h0, h1, h2, h3);
            *(uint4*)&AlF[s][1][t * 4] = make_uint4(l0, l1, l2, l3);
        }

        // ---- 2. prefetch A(it+1), both subs ----
        if (it + 1 < ntiles) {
            LOAD_A(v0);
            LOAD_A(v1);
        }

        // ---- 3. wait B(it), barrier ----
        cp_wait<0>();
        __syncthreads();

        // ---- 4. issue B(it+1) into stage s^1 ----
        if (it + 1 < ntiles) {
            cp16(bsB + (s ^ 1) * 8192, Wsrc);
            cp16(bsB + (s ^ 1) * 8192 + 4096, Wsrc + WstepB);
            cp_commit();
            Wsrc += 2 * WstepB;
        }

        // ---- 5. fragments + 2x24 MMA on buffer s, TERM-MAJOR order ----
#pragma unroll
        for (int sub = 0; sub < 2; ++sub) {
            uint32_t ah[2][4], al[2][4], bh[4][2], bl[4][2];
#pragma unroll
            for (int mi = 0; mi < 2; ++mi) {
                const int mt = wmi * 2 + mi;
                uint4 a4 = *(const uint4*)&AhF[s][sub][(mt * 32 + lane) * 4];
                ah[mi][0] = a4.x; ah[mi][1] = a4.y; ah[mi][2] = a4.z; ah[mi][3] = a4.w;
                uint4 b4 = *(const uint4*)&AlF[s][sub][(mt * 32 + lane) * 4];
                al[mi][0] = b4.x; al[mi][1] = b4.y; al[mi][2] = b4.z; al[mi][3] = b4.w;
            }
#pragma unroll
            for (int p = 0; p < 2; ++p) {
                uint32_t (*bf)[2] = p ? bl : bh;
                uint4 q0 = *(const uint4*)&BF[s][sub][p * 512 + wt * 256 + lane * 4];
                uint4 q1 = *(const uint4*)&BF[s][sub][p * 512 + wt * 256 + 128 + lane * 4];
                bf[0][0] = q0.x; bf[0][1] = q0.y; bf[1][0] = q0.z; bf[1][1] = q0.w;
                bf[2][0] = q1.x; bf[2][1] = q1.y; bf[3][0] = q1.z; bf[3][1] = q1.w;
            }
            // Term-major: 8 independent accumulators between dependent MMAs.
            // Per-accumulator term order is unchanged (hh -> hl -> lh),
            // so the numerical result is bitwise identical to v6.
#pragma unroll
            for (int p = 0; p < 3; ++p) {
#pragma unroll
                for (int mi = 0; mi < 2; ++mi) {
#pragma unroll
                    for (int ni = 0; ni < 4; ++ni) {
                        const uint32_t* ap = (p == 2) ? al[mi] : ah[mi];
                        const uint32_t* bp = (p == 1) ? bl[ni] : bh[ni];
                        mma_bf16(acc[mi][ni], ap, bp);
                    }
                }
            }
        }
        // reads of buffer s complete before the next barrier, which precedes
        // the overwrite of s two iterations later.
    }

#undef LOAD_A

    // ---- epilogue: scatter into out[b, g, off + v*d + m] ----
#pragma unroll
    for (int mi = 0; mi < 2; ++mi) {
#pragma unroll
        for (int cr = 0; cr < 2; ++cr) {
            const int row = bm * 128 + wmi * 32 + mi * 16 + g + cr * 8;
            const int b = row / d;
            const int mm = row - b * d;
            float* ob = out + b * FS + offl + mm;
#pragma unroll
            for (int ni = 0; ni < 4; ++ni) {
#pragma unroll
                for (int cc = 0; cc < 2; ++cc) {
                    const int col = bn * 64 + wt * 32 + ni * 8 + tg * 2 + cc;
                    const int gg = col / d;
                    const int vv = col - gg * d;
                    ob[gg * IR + vv * d] = acc[mi][ni][cr * 2 + cc];
                }
            }
        }
    }
}

// ---------------------------------------------------------------------------
extern "C" void kernel_launch(void* const* d_in, const int* in_sizes, int n_in,
                              void* d_out, int out_size)
{
    const float* x = nullptr;
    const float* D = nullptr;
    const float* w = nullptr;
    for (int i = 0; i < n_in; ++i) {
        if (in_sizes[i] == NROT * IR)         D = (const float*)d_in[i];
        else if (in_sizes[i] == F * F * NROT) w = (const float*)d_in[i];
        else                                  x = (const float*)d_in[i];
    }
    float* out = (float*)d_out;

    build_w2_kernel<<<dim3(8, 64), 256>>>(D, w);
    pack_w2_kernel<<<dim3(2704, LMAX + 1), 256>>>();
    so3_v8_kernel<<<3640, 256>>>(x, out);
}

// round 15
// speedup vs baseline: 1.4862x; 1.0036x over previous
#include <cuda_runtime.h>
#include <cstdint>

#define LMAX  6
#define BATCH 1024
#define F     64
#define IR    455
#define NROT  64
#define FS    (F * IR)   // 29120 floats per batch element

// Raw packed pre-scaled weights W_l[k, n] (f32), k=(f*d+u), n=(g*d+v).
__device__ float g_W[4096 * 455];
// Fragment-ordered bf16x2 hi/lo planes of W.
// Per l (offset 4096*off[l] u32): idx = j + 4*lane + 128*c + 256*wt + 512*pl + 1024*(bn + d*kt)
__device__ uint32_t g_Wf[4096 * 455];

// Tile decode tables, ordered l = 6..0 (largest K first).
__constant__ int c_cnt[7]  = {1352, 968, 648, 392, 200, 72, 8}; // 8*d*d
__constant__ int c_d[7]    = {13, 11, 9, 7, 5, 3, 1};
__constant__ int c_off[7]  = {286, 165, 84, 35, 10, 1, 0};

// ---------------------------------------------------------------------------
// helpers
// ---------------------------------------------------------------------------
__device__ __forceinline__ uint32_t pack_bf16x2(float lo_e, float hi_e) {
    uint32_t r;
    asm("cvt.rn.bf16x2.f32 %0, %1, %2;" : "=r"(r) : "f"(hi_e), "f"(lo_e));
    return r;
}
__device__ __forceinline__ float bf16_lo_f32(uint32_t p) { return __uint_as_float(p << 16); }
__device__ __forceinline__ float bf16_hi_f32(uint32_t p) { return __uint_as_float(p & 0xffff0000u); }

__device__ __forceinline__ uint32_t split_pack(float e0, float e1, uint32_t& lo_out) {
    uint32_t hi = pack_bf16x2(e0, e1);
    lo_out = pack_bf16x2(e0 - bf16_lo_f32(hi), e1 - bf16_hi_f32(hi));
    return hi;
}

__device__ __forceinline__ void mma_bf16(float c[4],
                                         const uint32_t a[4],
                                         const uint32_t b[2])
{
    asm volatile(
        "mma.sync.aligned.m16n8k16.row.col.f32.bf16.bf16.f32 "
        "{%0,%1,%2,%3}, {%4,%5,%6,%7}, {%8,%9}, {%0,%1,%2,%3};"
        : "+f"(c[0]), "+f"(c[1]), "+f"(c[2]), "+f"(c[3])
        : "r"(a[0]), "r"(a[1]), "r"(a[2]), "r"(a[3]), "r"(b[0]), "r"(b[1]));
}

__device__ __forceinline__ void cp16(uint32_t s, const void* g) {
    asm volatile("cp.async.cg.shared.global [%0], [%1], 16;" :: "r"(s), "l"(g));
}
__device__ __forceinline__ void cp_commit() { asm volatile("cp.async.commit_group;"); }
template <int W>
__device__ __forceinline__ void cp_wait() { asm volatile("cp.async.wait_group %0;" :: "n"(W)); }

// ---------------------------------------------------------------------------
// Kernel 1: psi GEMM.  C[fg, i] = sum_r w[fg, r] * D[r, i], scattered into g_W.
// grid = (8, 64)
// ---------------------------------------------------------------------------
__global__ void __launch_bounds__(256) build_w2_kernel(const float* __restrict__ D,
                                                       const float* __restrict__ w)
{
    const int dtab[7] = {1, 3, 5, 7, 9, 11, 13};
    const int otab[7] = {0, 1, 10, 35, 84, 165, 286};

    __shared__ float Wsh[64][68];
    __shared__ float Dsh[64][68];

    const int t   = threadIdx.x;
    const int fg0 = blockIdx.y * 64;
    const int i0  = blockIdx.x * 64;

    for (int idx = t; idx < 4096; idx += 256) {
        int row = idx >> 6, r = idx & 63;
        Wsh[r][row] = w[(fg0 + row) * 64 + r];
    }
    for (int idx = t; idx < 4096; idx += 256) {
        int r = idx >> 6, c = idx & 63;
        int i = i0 + c;
        Dsh[r][c] = (i < IR) ? D[r * IR + i] : 0.0f;
    }
    __syncthreads();

    const int ty = t >> 4, tx = t & 15;
    float acc[4][4] = {};

#pragma unroll 4
    for (int r = 0; r < 64; ++r) {
        float4 a4 = *(const float4*)&Wsh[r][ty * 4];
        float4 b4 = *(const float4*)&Dsh[r][tx * 4];
        float av[4] = {a4.x, a4.y, a4.z, a4.w};
        float bv[4] = {b4.x, b4.y, b4.z, b4.w};
#pragma unroll
        for (int i = 0; i < 4; ++i)
#pragma unroll
            for (int j = 0; j < 4; ++j)
                acc[i][j] += av[i] * bv[j];
    }

#pragma unroll
    for (int j = 0; j < 4; ++j) {
        const int i = i0 + tx * 4 + j;
        if (i >= IR) continue;
        int l = 0;
#pragma unroll
        for (int q = 1; q < 7; ++q)
            if (i >= otab[q]) l = q;
        const int d = dtab[l], off = otab[l];
        const int jj = i - off;
        const int u = jj / d, v = jj - u * d;
        const float scale = rsqrtf((float)d) * (1.0f / 64.0f);
        const int base = 4096 * off;
        const int N = 64 * d;
#pragma unroll
        for (int i4 = 0; i4 < 4; ++i4) {
            const int fg = fg0 + ty * 4 + i4;
            const int f = fg >> 6, gg = fg & 63;
            g_W[base + (f * d + u) * N + gg * d + v] = scale * acc[i4][j];
        }
    }
}

// ---------------------------------------------------------------------------
// Kernel 1b: pack g_W into fragment-ordered planes — coalesced flat version.
// One thread per (k2, n) pair; reads two consecutive-k rows coalesced,
// writes hi+lo via the inverse fragment mapping.
// grid = 3640 blocks x 256 (2048*455 pairs exactly).
// ---------------------------------------------------------------------------
__global__ void __launch_bounds__(256) pack_w3_kernel()
{
    const int dtab[7] = {1, 3, 5, 7, 9, 11, 13};
    const int otab[7] = {0, 1, 10, 35, 84, 165, 286};

    const int p = blockIdx.x * 256 + threadIdx.x;   // [0, 2048*455)

    int l = 0;
#pragma unroll
    for (int q = 1; q < 7; ++q)
        if (p >= 2048 * otab[q]) l = q;
    const int d    = dtab[l];
    const int N    = 64 * d;
    const int base = 4096 * otab[l];
    const int local = p - 2048 * otab[l];
    const int k2 = local / N;
    const int n  = local - k2 * N;

    const float e0 = g_W[base + (2 * k2) * N + n];
    const float e1 = g_W[base + (2 * k2 + 1) * N + n];
    uint32_t lo;
    uint32_t hi = split_pack(e0, e1, lo);

    // inverse fragment mapping (validated against pack_w2's forward map)
    const int kt = k2 >> 3;
    const int r  = k2 & 7;
    const int tg = r & 3;
    const int j1 = r >> 2;
    const int bn = n >> 6;
    const int nl = n & 63;
    const int wt = nl >> 5;
    const int q2 = (nl >> 3) & 3;    // 2c + j2
    const int cc = q2 >> 1;
    const int j2 = q2 & 1;
    const int g  = nl & 7;
    const int j  = (j2 << 1) | j1;
    const int lane = g * 4 + tg;

    const int idx0 = j + 4 * lane + 128 * cc + 256 * wt + 1024 * (bn + d * kt);
    g_Wf[base + idx0]       = hi;
    g_Wf[base + idx0 + 512] = lo;
}

// ---------------------------------------------------------------------------
// Kernel 2: fused GEMM, bf16x2-split, fragment-ordered operands, BK=32.
// RESTRUCTURED PIPELINE: A split+STS for tile it+1 executes AFTER the barrier,
// interleaved with MMA(it) — the pre-barrier critical path is just cp_wait.
// Block tile 128x64, 256 threads = 8 warps (4x2 of 32x32 warp tiles).
// ---------------------------------------------------------------------------
__global__ void __launch_bounds__(256) so3_v9_kernel(const float* __restrict__ x,
                                                     float* __restrict__ out)
{
    // ---- decode (l, bm, bn) ----
    int rem = blockIdx.x;
    int li = 0;
#pragma unroll
    for (int q = 0; q < 6; ++q)
        if (rem >= c_cnt[li]) { rem -= c_cnt[li]; li++; }
    const int d    = c_d[li];
    const int offl = c_off[li];
    const int bn   = rem % d;
    const int bm   = rem / d;

    const int K = 64 * d;

    // [stage][sub][1024], 16B-stride-per-lane fragment order (conflict-free)
    __shared__ __align__(16) uint32_t AhF[2][2][1024];   // 16 KB
    __shared__ __align__(16) uint32_t AlF[2][2][1024];   // 16 KB
    __shared__ __align__(16) uint32_t BF [2][2][1024];   // 16 KB

    const int t    = threadIdx.x;
    const int wid  = t >> 5;
    const int lane = t & 31;
    const int g    = lane >> 2;
    const int tg   = lane & 3;
    const int wmi  = wid & 3;          // warp m index (32-row tiles)
    const int wt   = wid >> 2;         // warp n half (32 cols)

    // ---- direct A gather mapping: this thread's fragment slot ----
    const int m    = (t >> 5) * 16 + g;
    const int gr0  = bm * 128 + m;
    const int gr8  = gr0 + 8;
    const int b0_  = gr0 / d;
    const int b8_  = gr8 / d;
    const float* base0 = x + b0_ * FS + offl + (gr0 - b0_ * d);
    const float* base8 = x + b8_ * FS + offl + (gr8 - b8_ * d);

    const int q16 = 16 / d;
    const int r16 = 16 - q16 * d;
    const int kl[4] = {2 * tg, 2 * tg + 1, 2 * tg + 8, 2 * tg + 9};
    int uA[4], offA[4];
#pragma unroll
    for (int j = 0; j < 4; ++j) {
        const int f = kl[j] / d;
        uA[j]   = kl[j] - f * d;
        offA[j] = f * IR + uA[j] * d;
    }

    // ---- B staging ----
    const uint32_t* Wsrc = g_Wf + 4096 * offl + bn * 1024 + t * 4;
    const int WstepB = d * 1024;   // u32 per k16 sub-tile

    const uint32_t bf_b = (uint32_t)__cvta_generic_to_shared(&BF[0][0][0]);
    const uint32_t bsB  = bf_b + t * 16;

    float acc[2][4][4] = {};
    float v0[8], v1[8];

#define LOAD_A(dst)                                                     \
    do {                                                                \
        dst[0] = base0[offA[0]]; dst[1] = base0[offA[1]];               \
        dst[2] = base8[offA[0]]; dst[3] = base8[offA[1]];               \
        dst[4] = base0[offA[2]]; dst[5] = base0[offA[3]];               \
        dst[6] = base8[offA[2]]; dst[7] = base8[offA[3]];               \
        _Pragma("unroll")                                               \
        for (int j = 0; j < 4; ++j) {                                   \
            uA[j] += r16; offA[j] += q16 * IR + r16 * d;                \
            if (uA[j] >= d) { uA[j] -= d; offA[j] += IR - d * d; }      \
        }                                                               \
    } while (0)

#define STS_A(st)                                                       \
    do {                                                                \
        uint32_t l0, l1, l2, l3;                                        \
        uint32_t h0 = split_pack(v0[0], v0[1], l0);                     \
        uint32_t h1 = split_pack(v0[2], v0[3], l1);                     \
        uint32_t h2 = split_pack(v0[4], v0[5], l2);                     \
        uint32_t h3 = split_pack(v0[6], v0[7], l3);                     \
        *(uint4*)&AhF[st][0][t * 4] = make_uint4(h0, h1, h2, h3);       \
        *(uint4*)&AlF[st][0][t * 4] = make_uint4(l0, l1, l2, l3);       \
        h0 = split_pack(v1[0], v1[1], l0);                              \
        h1 = split_pack(v1[2], v1[3], l1);                              \
        h2 = split_pack(v1[4], v1[5], l2);                              \
        h3 = split_pack(v1[6], v1[7], l3);                              \
        *(uint4*)&AhF[st][1][t * 4] = make_uint4(h0, h1, h2, h3);       \
        *(uint4*)&AlF[st][1][t * 4] = make_uint4(l0, l1, l2, l3);       \
    } while (0)

    // ---- prologue ----
    LOAD_A(v0); LOAD_A(v1);     // A(0)
    STS_A(0);                   // stage A(0) into stage 0
    LOAD_A(v0); LOAD_A(v1);     // A(1) held in regs, stored during iter 0
    cp16(bsB, Wsrc);            // B(0) into stage 0
    cp16(bsB + 4096, Wsrc + WstepB);
    cp_commit();
    Wsrc += 2 * WstepB;

    const int ntiles = K >> 5;  // k32 tiles = 2d  (>= 2 for all l)
    for (int it = 0; it < ntiles; ++it) {
        const int s = it & 1;

        // ---- 1. wait B(it) (issued one full iteration ago), barrier ----
        cp_wait<0>();
        __syncthreads();

        // ---- 2. issue B(it+1) into stage s^1 ----
        if (it + 1 < ntiles) {
            cp16(bsB + (s ^ 1) * 8192, Wsrc);
            cp16(bsB + (s ^ 1) * 8192 + 4096, Wsrc + WstepB);
            cp_commit();
            Wsrc += 2 * WstepB;
        }

        // ---- 3. fragments + 2x24 MMA on buffer s ----
#pragma unroll
        for (int sub = 0; sub < 2; ++sub) {
            uint32_t ah[2][4], al[2][4], bh[4][2], bl[4][2];
#pragma unroll
            for (int mi = 0; mi < 2; ++mi) {
                const int mt = wmi * 2 + mi;
                uint4 a4 = *(const uint4*)&AhF[s][sub][(mt * 32 + lane) * 4];
                ah[mi][0] = a4.x; ah[mi][1] = a4.y; ah[mi][2] = a4.z; ah[mi][3] = a4.w;
                uint4 b4 = *(const uint4*)&AlF[s][sub][(mt * 32 + lane) * 4];
                al[mi][0] = b4.x; al[mi][1] = b4.y; al[mi][2] = b4.z; al[mi][3] = b4.w;
            }
#pragma unroll
            for (int p = 0; p < 2; ++p) {
                uint32_t (*bf)[2] = p ? bl : bh;
                uint4 q0 = *(const uint4*)&BF[s][sub][p * 512 + wt * 256 + lane * 4];
                uint4 q1 = *(const uint4*)&BF[s][sub][p * 512 + wt * 256 + 128 + lane * 4];
                bf[0][0] = q0.x; bf[0][1] = q0.y; bf[1][0] = q0.z; bf[1][1] = q0.w;
                bf[2][0] = q1.x; bf[2][1] = q1.y; bf[3][0] = q1.z; bf[3][1] = q1.w;
            }
#pragma unroll
            for (int p = 0; p < 3; ++p) {
#pragma unroll
                for (int mi = 0; mi < 2; ++mi) {
#pragma unroll
                    for (int ni = 0; ni < 4; ++ni) {
                        const uint32_t* ap = (p == 2) ? al[mi] : ah[mi];
                        const uint32_t* bp = (p == 1) ? bl[ni] : bh[ni];
                        mma_bf16(acc[mi][ni], ap, bp);
                    }
                }
            }
        }

        // ---- 4. split+STS A(it+1) into stage s^1 (overlaps MMA issue) ----
        // s^1 was last READ at iter it-1; all warps passed barrier(it) -> safe.
        // Next read is after barrier(it+1) -> ordered.
        if (it + 1 < ntiles) {
            STS_A(s ^ 1);
            // ---- 5. prefetch A(it+2) into regs ----
            if (it + 2 < ntiles) {
                LOAD_A(v0); LOAD_A(v1);
            }
        }
    }

#undef LOAD_A
#undef STS_A

    // ---- epilogue: scatter into out[b, g, off + v*d + m] ----
#pragma unroll
    for (int mi = 0; mi < 2; ++mi) {
#pragma unroll
        for (int cr = 0; cr < 2; ++cr) {
            const int row = bm * 128 + wmi * 32 + mi * 16 + g + cr * 8;
            const int b = row / d;
            const int mm = row - b * d;
            float* ob = out + b * FS + offl + mm;
#pragma unroll
            for (int ni = 0; ni < 4; ++ni) {
#pragma unroll
                for (int cc = 0; cc < 2; ++cc) {
                    const int col = bn * 64 + wt * 32 + ni * 8 + tg * 2 + cc;
                    const int gg = col / d;
                    const int vv = col - gg * d;
                    ob[gg * IR + vv * d] = acc[mi][ni][cr * 2 + cc];
                }
            }
        }
    }
}

// ---------------------------------------------------------------------------
extern "C" void kernel_launch(void* const* d_in, const int* in_sizes, int n_in,
                              void* d_out, int out_size)
{
    const float* x = nullptr;
    const float* D = nullptr;
    const float* w = nullptr;
    for (int i = 0; i < n_in; ++i) {
        if (in_sizes[i] == NROT * IR)         D = (const float*)d_in[i];
        else if (in_sizes[i] == F * F * NROT) w = (const float*)d_in[i];
        else                                  x = (const float*)d_in[i];
    }
    float* out = (float*)d_out;

    build_w2_kernel<<<dim3(8, 64), 256>>>(D, w);
    pack_w3_kernel<<<3640, 256>>>();     // 2048*455 / 256 exactly
    so3_v9_kernel<<<3640, 256>>>(x, out);
}